// round 16
// baseline (speedup 1.0000x reference)
#include <cuda_runtime.h>
#include <cuda_fp16.h>
#include <cstdint>

#define HID 512
#define BAT 32
#define TLEN 512
#define G4 2048
#define NBLK 128
#define NBLK_DIR 64
#define HP 40    // scan ht2s row pitch (uint32): conflict-free
#define RP2 36   // scan red row pitch (floats): finalize banks bijective
#define GP2 36   // gemm smem row pitch (uint32): LDSM banks 4r+off distinct

#define X_WORDS (16384 * 256)
#define W_WORDS (2048 * 256)

#define TILEW (128 * GP2)            // words per tile (one 64-k chunk)
#define TILEB (TILEW * 4)            // bytes per tile
#define GSM_BYTES (4 * TILEB)        // A0,B0,A1,B1 = 73728 B

// ----------------------------------------------------------------------------
// Scratch (static __device__ — no allocations allowed)
// ----------------------------------------------------------------------------
__device__ float    g_xg[2][TLEN][BAT][G4];    // xg[dir][t][b][gate]
__device__ uint32_t g_h2[2][2][256][32];       // [parity][dir][kp][b] packed half2
__device__ unsigned g_cnt[2][32];              // [dir][0] monotonic arrival counter
__device__ uint32_t g_xh2[X_WORDS];            // x as half2 k-pairs [m][kp], m=b*512+t
__device__ uint32_t g_wh2[2][W_WORDS];         // Wih as half2 k-pairs [n][kp]

// ----------------------------------------------------------------------------
// helpers
// ----------------------------------------------------------------------------
__device__ __forceinline__ float fex2(float x)
{ float y; asm("ex2.approx.f32 %0, %1;" : "=f"(y) : "f"(x)); return y; }
__device__ __forceinline__ float frcp(float x)
{ float y; asm("rcp.approx.f32 %0, %1;" : "=f"(y) : "f"(x)); return y; }

__device__ __forceinline__ float fsigmoid(float x)
{ return frcp(1.f + fex2(-1.4426950408889634f * x)); }
__device__ __forceinline__ float ftanh(float x)
{
    float ax = fabsf(x);
    float e = fex2(-2.8853900817779268f * ax);
    float t = 1.f - 2.f * e * frcp(1.f + e);
    return copysignf(t, x);
}

__device__ __forceinline__ void red_add_release(unsigned* p)
{ asm volatile("red.release.gpu.global.add.u32 [%0], 1;" :: "l"(p) : "memory"); }
__device__ __forceinline__ unsigned ld_acquire(const unsigned* p)
{ unsigned v; asm volatile("ld.acquire.gpu.global.u32 %0, [%1];" : "=r"(v) : "l"(p) : "memory"); return v; }

__device__ __forceinline__ uint32_t pack_h2(float a, float b)
{
    __half2 h = __floats2half2_rn(a, b);
    return *(uint32_t*)&h;
}

__device__ __forceinline__ void mma16816(float& d0, float& d1, float& d2, float& d3,
                                         uint32_t a0, uint32_t a1, uint32_t a2, uint32_t a3,
                                         uint32_t b0, uint32_t b1)
{
    asm("mma.sync.aligned.m16n8k16.row.col.f32.f16.f16.f32 "
        "{%0,%1,%2,%3}, {%4,%5,%6,%7}, {%8,%9}, {%0,%1,%2,%3};"
        : "+f"(d0), "+f"(d1), "+f"(d2), "+f"(d3)
        : "r"(a0), "r"(a1), "r"(a2), "r"(a3), "r"(b0), "r"(b1));
}

__device__ __forceinline__ void ldsm_x4(uint32_t& r0, uint32_t& r1,
                                        uint32_t& r2, uint32_t& r3, uint32_t addr)
{
    asm volatile("ldmatrix.sync.aligned.m8n8.x4.shared.b16 {%0,%1,%2,%3}, [%4];"
                 : "=r"(r0), "=r"(r1), "=r"(r2), "=r"(r3) : "r"(addr));
}

__device__ __forceinline__ uint32_t smem_u32(const void* p)
{
    uint32_t a;
    asm("{ .reg .u64 t; cvta.to.shared.u64 t, %1; cvt.u32.u64 %0, t; }"
        : "=r"(a) : "l"(p));
    return a;
}

__device__ __forceinline__ void cp16(uint32_t dst, const void* src)
{ asm volatile("cp.async.cg.shared.global [%0], [%1], 16;" :: "r"(dst), "l"(src) : "memory"); }
__device__ __forceinline__ void cp_commit()
{ asm volatile("cp.async.commit_group;" ::: "memory"); }
__device__ __forceinline__ void cp_wait1()
{ asm volatile("cp.async.wait_group 1;" ::: "memory"); }
__device__ __forceinline__ void cp_wait0()
{ asm volatile("cp.async.wait_group 0;" ::: "memory"); }

// ----------------------------------------------------------------------------
// Kernel 0: convert x / Wih_f / Wih_b to half2 k-pair layout.
// Block 0 also zeroes the scan arrival counters.
// ----------------------------------------------------------------------------
__global__ void __launch_bounds__(256) cvt_kernel(
    const float* __restrict__ x,
    const float* __restrict__ Wf,
    const float* __restrict__ Wb)
{
    if (blockIdx.x == 0 && threadIdx.x < 64)
        ((unsigned*)g_cnt)[threadIdx.x] = 0u;

    size_t w = ((size_t)blockIdx.x * 256 + threadIdx.x) * 8;
    const float* src;
    uint32_t* dst;
    if (w < X_WORDS)                     { src = x  + 2 * w;               dst = g_xh2 + w; }
    else if (w < X_WORDS + W_WORDS)      { src = Wf + 2 * (w - X_WORDS);   dst = g_wh2[0] + (w - X_WORDS); }
    else                                 { src = Wb + 2 * (w - X_WORDS - W_WORDS);
                                           dst = g_wh2[1] + (w - X_WORDS - W_WORDS); }
    const float4* s = (const float4*)src;
    #pragma unroll
    for (int i = 0; i < 4; i++) {
        float4 v = s[i];
        dst[2 * i]     = pack_h2(v.x, v.y);
        dst[2 * i + 1] = pack_h2(v.z, v.w);
    }
}

// ----------------------------------------------------------------------------
// Kernel 1: tensor-core input GEMM — cp.async double-buffered, K-chunk = 64
// (R15, proven).
// ----------------------------------------------------------------------------
__global__ void __launch_bounds__(256, 2) gemm_xg_tc_kernel(
    const float* __restrict__ bihf, const float* __restrict__ bhhf,
    const float* __restrict__ bihb, const float* __restrict__ bhhb)
{
    extern __shared__ uint32_t gsm[];

    const int dir = blockIdx.z;
    const int n0 = blockIdx.x * 128;
    const int m0 = blockIdx.y * 128;
    const uint32_t* __restrict__ A = g_xh2 + (size_t)m0 * 256;
    const uint32_t* __restrict__ B = g_wh2[dir] + (size_t)n0 * 256;
    const float* __restrict__ bih = dir ? bihb : bihf;
    const float* __restrict__ bhh = dir ? bhhb : bhhf;

    const int tid = threadIdx.x;
    const int warp = tid >> 5, lane = tid & 31;
    const int g = lane >> 2, c = lane & 3;
    const int wm = warp & 3;
    const int wn = warp >> 2;

    const int qq = lane >> 3;
    const int rr = lane & 7;
    const uint32_t base = smem_u32(gsm);
    const uint32_t a_off0 = ((wm * 32 + (qq & 1) * 8 + rr) * GP2 + (qq >> 1) * 4) * 4u;
    const uint32_t b_off0 = (uint32_t)TILEB +
                            ((wn * 64 + (qq >> 1) * 8 + rr) * GP2 + (qq & 1) * 4) * 4u;

    const int lr = tid >> 1;
    const int lh = tid & 1;
    const uint32_t dstA0 = base + (lr * GP2 + lh * 16) * 4u;
    const size_t srcoff = (size_t)lr * 256 + lh * 16;

    float acc[2][8][4];
    #pragma unroll
    for (int mt = 0; mt < 2; mt++)
        #pragma unroll
        for (int nt = 0; nt < 8; nt++)
            #pragma unroll
            for (int q = 0; q < 4; q++) acc[mt][nt][q] = 0.f;

    auto load_chunk = [&](int kc, int b) {
        uint32_t dA = dstA0 + b * 2 * TILEB;
        uint32_t dB = dA + TILEB;
        const uint32_t* sA = A + srcoff + kc * 32;
        const uint32_t* sB = B + srcoff + kc * 32;
        #pragma unroll
        for (int q = 0; q < 4; q++) {
            cp16(dA + q * 16, sA + q * 4);
            cp16(dB + q * 16, sB + q * 4);
        }
    };

    load_chunk(0, 0);
    cp_commit();

    for (int kc = 0; kc < 8; kc++) {
        if (kc < 7) {
            load_chunk(kc + 1, (kc + 1) & 1);
            cp_commit();
            cp_wait1();
        } else {
            cp_wait0();
        }
        __syncthreads();

        const uint32_t bufb = base + (kc & 1) * 2 * TILEB;
        #pragma unroll
        for (int ks = 0; ks < 4; ks++) {
            const uint32_t ksb = bufb + ks * 32u;
            uint32_t af[2][4];
            #pragma unroll
            for (int mt = 0; mt < 2; mt++)
                ldsm_x4(af[mt][0], af[mt][1], af[mt][2], af[mt][3],
                        ksb + a_off0 + mt * (16 * GP2 * 4u));
            uint32_t bf[4][4];
            #pragma unroll
            for (int p = 0; p < 4; p++)
                ldsm_x4(bf[p][0], bf[p][1], bf[p][2], bf[p][3],
                        ksb + b_off0 + p * (16 * GP2 * 4u));
            #pragma unroll
            for (int nt = 0; nt < 8; nt++) {
                uint32_t b0 = bf[nt >> 1][(nt & 1) * 2 + 0];
                uint32_t b1 = bf[nt >> 1][(nt & 1) * 2 + 1];
                #pragma unroll
                for (int mt = 0; mt < 2; mt++)
                    mma16816(acc[mt][nt][0], acc[mt][nt][1], acc[mt][nt][2], acc[mt][nt][3],
                             af[mt][0], af[mt][1], af[mt][2], af[mt][3], b0, b1);
            }
        }
        __syncthreads();
    }

    float bias0[8], bias1[8];
    #pragma unroll
    for (int nt = 0; nt < 8; nt++) {
        int n = n0 + wn * 64 + nt * 8 + 2 * c;
        bias0[nt] = bih[n] + bhh[n];
        bias1[nt] = bih[n + 1] + bhh[n + 1];
    }
    #pragma unroll
    for (int mt = 0; mt < 2; mt++) {
        #pragma unroll
        for (int rw = 0; rw < 2; rw++) {
            int m = m0 + wm * 32 + mt * 16 + g + rw * 8;
            int t = m & 511;
            int b = m >> 9;
            float* o = &g_xg[dir][t][b][n0 + wn * 64];
            #pragma unroll
            for (int nt = 0; nt < 8; nt++) {
                float2 v = make_float2(acc[mt][nt][rw * 2 + 0] + bias0[nt],
                                       acc[mt][nt][rw * 2 + 1] + bias1[nt]);
                *(float2*)&o[nt * 8 + 2 * c] = v;
            }
        }
    }
}

// ----------------------------------------------------------------------------
// Kernel 2: persistent scan — R10 core, de-layered sync tail:
//   publish warps: STG -> __syncwarp (lane fence) -> lane0 red.release
//     (8 arrivals/block; target (s+1)*64*8)
//   all warps: all-lane ld.acquire poll (1 coalesced req/warp) -> own reload
//   2 block barriers per step instead of 4.
// ----------------------------------------------------------------------------
#define SMEM_WORDS (256 * HP + 2 * 32 * RP2)   // 12544 words = 50176 B

__global__ void __launch_bounds__(512, 1) lstm_scan_kernel(
    const float* __restrict__ Whh_f,
    const float* __restrict__ Whh_b,
    float* __restrict__ out)
{
    extern __shared__ uint32_t smu[];
    uint32_t* ht2s = smu;                         // [256][HP]
    float*    red  = (float*)(smu + 256 * HP);    // [2][32][RP2]

    const int tid = threadIdx.x;
    const int dir = blockIdx.x >> 6;
    const int j0  = (blockIdx.x & 63) * 8;
    const float* __restrict__ Whh = dir ? Whh_b : Whh_f;

    const int warp = tid >> 5;
    const int lane = tid & 31;
    const int wm = warp & 1;
    const int kh = (warp >> 1) & 1;
    const int wn = warp >> 2;
    const int g  = lane >> 2;
    const int c  = lane & 3;

    uint32_t afrag[16][4];
    {
        int r0 = wm * 16 + g;
        const float* rowA = Whh + (size_t)((r0 >> 3) * 512 + j0 + (r0 & 7)) * 512;
        const float* rowB = Whh + (size_t)((((r0 + 8) >> 3)) * 512 + j0 + ((r0 + 8) & 7)) * 512;
        #pragma unroll
        for (int kt = 0; kt < 16; kt++) {
            int kb = kh * 256 + kt * 16 + 2 * c;
            afrag[kt][0] = pack_h2(rowA[kb],     rowA[kb + 1]);
            afrag[kt][1] = pack_h2(rowB[kb],     rowB[kb + 1]);
            afrag[kt][2] = pack_h2(rowA[kb + 8], rowA[kb + 9]);
            afrag[kt][3] = pack_h2(rowB[kb + 8], rowB[kb + 9]);
        }
    }

    for (int i = tid; i < 256 * HP; i += 512) ht2s[i] = 0u;

    const int fb = tid >> 3;
    const int fj = tid & 7;
    float c_state = 0.f;

    unsigned* cnt = &g_cnt[dir][0];
    const float* xg_base = &g_xg[dir][0][fb & 31][j0 + fj];
    float* out_base = out + (size_t)(fb & 31) * (TLEN * 1024) + dir * 512 + j0 + fj;
    uint32_t* h2_base0 = &g_h2[0][dir][(j0 + fj) >> 1][fb & 31];
    uint32_t* h2_base1 = &g_h2[1][dir][(j0 + fj) >> 1][fb & 31];

    __syncthreads();

    for (int s = 0; s < 512; s++) {
        const int t = dir ? (511 - s) : s;

        // prefetch xg (finalize threads only; consumed after the matmul)
        float xi = 0.f, xf = 0.f, xgv = 0.f, xo = 0.f;
        if (tid < 256) {
            const float* xgp = xg_base + (size_t)t * (BAT * G4);
            xi  = __ldcs(xgp);
            xf  = __ldcs(xgp + 512);
            xgv = __ldcs(xgp + 1024);
            xo  = __ldcs(xgp + 1536);
        }

        // two independent accumulator chains (kt even / odd)
        float d0 = 0.f, d1 = 0.f, d2 = 0.f, d3 = 0.f;
        float e0 = 0.f, e1 = 0.f, e2 = 0.f, e3 = 0.f;
        #pragma unroll
        for (int kt = 0; kt < 16; kt += 2) {
            int kp0 = kh * 128 + kt * 8;
            uint32_t b0 = ht2s[(kp0 + c) * HP + wn * 8 + g];
            uint32_t b1 = ht2s[(kp0 + 4 + c) * HP + wn * 8 + g];
            mma16816(d0, d1, d2, d3,
                     afrag[kt][0], afrag[kt][1], afrag[kt][2], afrag[kt][3], b0, b1);
            int kp1 = kp0 + 8;
            uint32_t b2 = ht2s[(kp1 + c) * HP + wn * 8 + g];
            uint32_t b3 = ht2s[(kp1 + 4 + c) * HP + wn * 8 + g];
            mma16816(e0, e1, e2, e3,
                     afrag[kt + 1][0], afrag[kt + 1][1], afrag[kt + 1][2], afrag[kt + 1][3], b2, b3);
        }

        {
            float* rp = red + kh * (32 * RP2) + (wm * 16 + g) * RP2 + wn * 8 + 2 * c;
            *(float2*)rp             = make_float2(d0 + e0, d1 + e1);
            *(float2*)(rp + 8 * RP2) = make_float2(d2 + e2, d3 + e3);
        }
        __syncthreads();   // bar1: red stores visible; also fences ht2s reuse

        float hval = 0.f;
        if (tid < 256) {
            float dd[4];
            #pragma unroll
            for (int gate = 0; gate < 4; gate++) {
                int off = (gate * 8 + fj) * RP2 + fb;
                dd[gate] = red[off] + red[32 * RP2 + off];
            }
            float ig = fsigmoid(xi  + dd[0]);
            float fg = fsigmoid(xf  + dd[1]);
            float gg = ftanh(xgv + dd[2]);
            float og = fsigmoid(xo  + dd[3]);
            c_state = fg * c_state + ig * gg;
            hval = og * ftanh(c_state);
        }

        if (s < 511) {
            if (tid < 256) {
                // publish packed half2 (even fj pairs with odd fj via shfl)
                float hpart = __shfl_xor_sync(0xffffffffu, hval, 1);
                if ((fj & 1) == 0) {
                    uint32_t v = pack_h2(hval, hpart);
                    *((s & 1) ? h2_base1 : h2_base0) = v;
                }
                __syncwarp();                       // fence: warp's STGs ordered
                if (lane == 0) red_add_release(cnt); // release covers warp's stores
                out_base[(size_t)t * 1024] = hval;  // off critical path
            }

            // all warps: coalesced all-lane acquire poll, then own-slice reload
            {
                const unsigned tgt = (unsigned)((s + 1) * NBLK_DIR * 8);
                while ((int)(ld_acquire(cnt) - tgt) < 0) { }
            }
            const uint32_t* src = &g_h2[s & 1][dir][0][0];
            #pragma unroll
            for (int i = 0; i < 16; i++) {
                int kp = warp * 16 + i;
                uint32_t v = __ldcg(&src[kp * 32 + lane]);
                ht2s[kp * HP + lane] = v;
            }
            __syncthreads();   // bar2: reloads visible to all warps' mma
        } else {
            if (tid < 256)
                out_base[(size_t)t * 1024] = hval;
        }
    }
}

// ----------------------------------------------------------------------------
// Launch
// ----------------------------------------------------------------------------
extern "C" void kernel_launch(void* const* d_in, const int* in_sizes, int n_in,
                              void* d_out, int out_size)
{
    (void)in_sizes; (void)n_in; (void)out_size;
    const float* x     = (const float*)d_in[0];
    const float* Wih_f = (const float*)d_in[1];
    const float* Whh_f = (const float*)d_in[2];
    const float* bih_f = (const float*)d_in[3];
    const float* bhh_f = (const float*)d_in[4];
    const float* Wih_b = (const float*)d_in[5];
    const float* Whh_b = (const float*)d_in[6];
    const float* bih_b = (const float*)d_in[7];
    const float* bhh_b = (const float*)d_in[8];
    float* out = (float*)d_out;

    static bool attr_set = false;
    if (!attr_set) {
        cudaFuncSetAttribute(lstm_scan_kernel,
                             cudaFuncAttributeMaxDynamicSharedMemorySize,
                             SMEM_WORDS * (int)sizeof(uint32_t));
        cudaFuncSetAttribute(gemm_xg_tc_kernel,
                             cudaFuncAttributeMaxDynamicSharedMemorySize,
                             GSM_BYTES);
        attr_set = true;
    }

    cvt_kernel<<<2560, 256>>>(x, Wih_f, Wih_b);
    dim3 ggrid(16, 128, 2);
    gemm_xg_tc_kernel<<<ggrid, 256, GSM_BYTES>>>(bih_f, bhh_f, bih_b, bhh_b);
    lstm_scan_kernel<<<NBLK, 512, SMEM_WORDS * sizeof(uint32_t)>>>(Whh_f, Whh_b, out);
}

// round 17
// speedup vs baseline: 1.7887x; 1.7887x over previous
#include <cuda_runtime.h>
#include <cuda_fp16.h>
#include <cstdint>

#define HID 512
#define BAT 32
#define TLEN 512
#define G4 2048
#define NBLK 128
#define NBLK_DIR 64
#define HP 40    // scan ht2s row pitch (uint32): conflict-free
#define RP2 36   // scan red row pitch (floats): finalize banks bijective
#define GP2 36   // gemm smem row pitch (uint32): LDSM banks 4r+off distinct

#define X_WORDS (16384 * 256)
#define W_WORDS (2048 * 256)

#define TILEW (128 * GP2)            // words per tile (one 64-k chunk)
#define TILEB (TILEW * 4)            // bytes per tile
#define GSM_BYTES (4 * TILEB)        // A0,B0,A1,B1 = 73728 B

// ----------------------------------------------------------------------------
// Scratch (static __device__ — no allocations allowed)
// ----------------------------------------------------------------------------
__device__ float    g_xg[2][TLEN][BAT][G4];    // xg[dir][t][b][gate]
__device__ uint32_t g_h2[2][2][256][32];       // [parity][dir][kp][b] packed half2
__device__ unsigned g_cnt[2][32];              // [dir][0] monotonic arrival counter
__device__ uint32_t g_xh2[X_WORDS];            // x as half2 k-pairs [m][kp], m=b*512+t
__device__ uint32_t g_wh2[2][W_WORDS];         // Wih as half2 k-pairs [n][kp]

// ----------------------------------------------------------------------------
// helpers
// ----------------------------------------------------------------------------
__device__ __forceinline__ float fex2(float x)
{ float y; asm("ex2.approx.f32 %0, %1;" : "=f"(y) : "f"(x)); return y; }
__device__ __forceinline__ float frcp(float x)
{ float y; asm("rcp.approx.f32 %0, %1;" : "=f"(y) : "f"(x)); return y; }

__device__ __forceinline__ float fsigmoid(float x)
{ return frcp(1.f + fex2(-1.4426950408889634f * x)); }
__device__ __forceinline__ float ftanh(float x)
{
    float ax = fabsf(x);
    float e = fex2(-2.8853900817779268f * ax);
    float t = 1.f - 2.f * e * frcp(1.f + e);
    return copysignf(t, x);
}

__device__ __forceinline__ void red_add_release(unsigned* p)
{ asm volatile("red.release.gpu.global.add.u32 [%0], 1;" :: "l"(p) : "memory"); }
__device__ __forceinline__ unsigned ld_acquire(const unsigned* p)
{ unsigned v; asm volatile("ld.acquire.gpu.global.u32 %0, [%1];" : "=r"(v) : "l"(p) : "memory"); return v; }

__device__ __forceinline__ uint32_t pack_h2(float a, float b)
{
    __half2 h = __floats2half2_rn(a, b);
    return *(uint32_t*)&h;
}

__device__ __forceinline__ void mma16816(float& d0, float& d1, float& d2, float& d3,
                                         uint32_t a0, uint32_t a1, uint32_t a2, uint32_t a3,
                                         uint32_t b0, uint32_t b1)
{
    asm("mma.sync.aligned.m16n8k16.row.col.f32.f16.f16.f32 "
        "{%0,%1,%2,%3}, {%4,%5,%6,%7}, {%8,%9}, {%0,%1,%2,%3};"
        : "+f"(d0), "+f"(d1), "+f"(d2), "+f"(d3)
        : "r"(a0), "r"(a1), "r"(a2), "r"(a3), "r"(b0), "r"(b1));
}

__device__ __forceinline__ void ldsm_x4(uint32_t& r0, uint32_t& r1,
                                        uint32_t& r2, uint32_t& r3, uint32_t addr)
{
    asm volatile("ldmatrix.sync.aligned.m8n8.x4.shared.b16 {%0,%1,%2,%3}, [%4];"
                 : "=r"(r0), "=r"(r1), "=r"(r2), "=r"(r3) : "r"(addr));
}

__device__ __forceinline__ uint32_t smem_u32(const void* p)
{
    uint32_t a;
    asm("{ .reg .u64 t; cvta.to.shared.u64 t, %1; cvt.u32.u64 %0, t; }"
        : "=r"(a) : "l"(p));
    return a;
}

__device__ __forceinline__ void cp16(uint32_t dst, const void* src)
{ asm volatile("cp.async.cg.shared.global [%0], [%1], 16;" :: "r"(dst), "l"(src) : "memory"); }
__device__ __forceinline__ void cp_commit()
{ asm volatile("cp.async.commit_group;" ::: "memory"); }
__device__ __forceinline__ void cp_wait0()
{ asm volatile("cp.async.wait_group 0;" ::: "memory"); }

// ----------------------------------------------------------------------------
// Kernel 0: convert x / Wih_f / Wih_b to half2 k-pair layout.
// Block 0 also zeroes the scan arrival counters.
// ----------------------------------------------------------------------------
__global__ void __launch_bounds__(256) cvt_kernel(
    const float* __restrict__ x,
    const float* __restrict__ Wf,
    const float* __restrict__ Wb)
{
    if (blockIdx.x == 0 && threadIdx.x < 64)
        ((unsigned*)g_cnt)[threadIdx.x] = 0u;

    size_t w = ((size_t)blockIdx.x * 256 + threadIdx.x) * 8;
    const float* src;
    uint32_t* dst;
    if (w < X_WORDS)                     { src = x  + 2 * w;               dst = g_xh2 + w; }
    else if (w < X_WORDS + W_WORDS)      { src = Wf + 2 * (w - X_WORDS);   dst = g_wh2[0] + (w - X_WORDS); }
    else                                 { src = Wb + 2 * (w - X_WORDS - W_WORDS);
                                           dst = g_wh2[1] + (w - X_WORDS - W_WORDS); }
    const float4* s = (const float4*)src;
    #pragma unroll
    for (int i = 0; i < 4; i++) {
        float4 v = s[i];
        dst[2 * i]     = pack_h2(v.x, v.y);
        dst[2 * i + 1] = pack_h2(v.z, v.w);
    }
}

// ----------------------------------------------------------------------------
// Kernel 1: tensor-core input GEMM — cp.async double-buffered, K-chunk = 64,
// SINGLE barrier per chunk (next-chunk cp.async issued after the barrier:
// every warp has finished computing on the buffer being overwritten).
// ----------------------------------------------------------------------------
__global__ void __launch_bounds__(256, 2) gemm_xg_tc_kernel(
    const float* __restrict__ bihf, const float* __restrict__ bhhf,
    const float* __restrict__ bihb, const float* __restrict__ bhhb)
{
    extern __shared__ uint32_t gsm[];

    const int dir = blockIdx.z;
    const int n0 = blockIdx.x * 128;
    const int m0 = blockIdx.y * 128;
    const uint32_t* __restrict__ A = g_xh2 + (size_t)m0 * 256;
    const uint32_t* __restrict__ B = g_wh2[dir] + (size_t)n0 * 256;
    const float* __restrict__ bih = dir ? bihb : bihf;
    const float* __restrict__ bhh = dir ? bhhb : bhhf;

    const int tid = threadIdx.x;
    const int warp = tid >> 5, lane = tid & 31;
    const int g = lane >> 2, c = lane & 3;
    const int wm = warp & 3;
    const int wn = warp >> 2;

    const int qq = lane >> 3;
    const int rr = lane & 7;
    const uint32_t base = smem_u32(gsm);
    const uint32_t a_off0 = ((wm * 32 + (qq & 1) * 8 + rr) * GP2 + (qq >> 1) * 4) * 4u;
    const uint32_t b_off0 = (uint32_t)TILEB +
                            ((wn * 64 + (qq >> 1) * 8 + rr) * GP2 + (qq & 1) * 4) * 4u;

    const int lr = tid >> 1;
    const int lh = tid & 1;
    const uint32_t dstA0 = base + (lr * GP2 + lh * 16) * 4u;
    const size_t srcoff = (size_t)lr * 256 + lh * 16;

    float acc[2][8][4];
    #pragma unroll
    for (int mt = 0; mt < 2; mt++)
        #pragma unroll
        for (int nt = 0; nt < 8; nt++)
            #pragma unroll
            for (int q = 0; q < 4; q++) acc[mt][nt][q] = 0.f;

    auto load_chunk = [&](int kc, int b) {
        uint32_t dA = dstA0 + b * 2 * TILEB;
        uint32_t dB = dA + TILEB;
        const uint32_t* sA = A + srcoff + kc * 32;
        const uint32_t* sB = B + srcoff + kc * 32;
        #pragma unroll
        for (int q = 0; q < 4; q++) {
            cp16(dA + q * 16, sA + q * 4);
            cp16(dB + q * 16, sB + q * 4);
        }
    };

    load_chunk(0, 0);
    cp_commit();

    for (int kc = 0; kc < 8; kc++) {
        cp_wait0();              // chunk kc resident
        __syncthreads();         // and all warps done with the other buffer
        if (kc < 7) {
            load_chunk(kc + 1, (kc + 1) & 1);   // overwrites buffer of kc-1 (safe)
            cp_commit();
        }

        const uint32_t bufb = base + (kc & 1) * 2 * TILEB;
        #pragma unroll
        for (int ks = 0; ks < 4; ks++) {
            const uint32_t ksb = bufb + ks * 32u;
            uint32_t af[2][4];
            #pragma unroll
            for (int mt = 0; mt < 2; mt++)
                ldsm_x4(af[mt][0], af[mt][1], af[mt][2], af[mt][3],
                        ksb + a_off0 + mt * (16 * GP2 * 4u));
            uint32_t bf[4][4];
            #pragma unroll
            for (int p = 0; p < 4; p++)
                ldsm_x4(bf[p][0], bf[p][1], bf[p][2], bf[p][3],
                        ksb + b_off0 + p * (16 * GP2 * 4u));
            #pragma unroll
            for (int nt = 0; nt < 8; nt++) {
                uint32_t b0 = bf[nt >> 1][(nt & 1) * 2 + 0];
                uint32_t b1 = bf[nt >> 1][(nt & 1) * 2 + 1];
                #pragma unroll
                for (int mt = 0; mt < 2; mt++)
                    mma16816(acc[mt][nt][0], acc[mt][nt][1], acc[mt][nt][2], acc[mt][nt][3],
                             af[mt][0], af[mt][1], af[mt][2], af[mt][3], b0, b1);
            }
        }
    }

    float bias0[8], bias1[8];
    #pragma unroll
    for (int nt = 0; nt < 8; nt++) {
        int n = n0 + wn * 64 + nt * 8 + 2 * c;
        bias0[nt] = bih[n] + bhh[n];
        bias1[nt] = bih[n + 1] + bhh[n + 1];
    }
    #pragma unroll
    for (int mt = 0; mt < 2; mt++) {
        #pragma unroll
        for (int rw = 0; rw < 2; rw++) {
            int m = m0 + wm * 32 + mt * 16 + g + rw * 8;
            int t = m & 511;
            int b = m >> 9;
            float* o = &g_xg[dir][t][b][n0 + wn * 64];
            #pragma unroll
            for (int nt = 0; nt < 8; nt++) {
                float2 v = make_float2(acc[mt][nt][rw * 2 + 0] + bias0[nt],
                                       acc[mt][nt][rw * 2 + 1] + bias1[nt]);
                *(float2*)&o[nt * 8 + 2 * c] = v;
            }
        }
    }
}

// ----------------------------------------------------------------------------
// Kernel 2: persistent scan — EXACT R10/R15 structure (best measured 1.353 ms).
// One release + one poller per block; 4 block barriers per step.
// ----------------------------------------------------------------------------
#define SMEM_WORDS (256 * HP + 2 * 32 * RP2)   // 12544 words = 50176 B

__global__ void __launch_bounds__(512, 1) lstm_scan_kernel(
    const float* __restrict__ Whh_f,
    const float* __restrict__ Whh_b,
    float* __restrict__ out)
{
    extern __shared__ uint32_t smu[];
    uint32_t* ht2s = smu;                         // [256][HP]
    float*    red  = (float*)(smu + 256 * HP);    // [2][32][RP2]

    const int tid = threadIdx.x;
    const int dir = blockIdx.x >> 6;
    const int j0  = (blockIdx.x & 63) * 8;
    const float* __restrict__ Whh = dir ? Whh_b : Whh_f;

    const int warp = tid >> 5;
    const int lane = tid & 31;
    const int wm = warp & 1;
    const int kh = (warp >> 1) & 1;
    const int wn = warp >> 2;
    const int g  = lane >> 2;
    const int c  = lane & 3;

    uint32_t afrag[16][4];
    {
        int r0 = wm * 16 + g;
        const float* rowA = Whh + (size_t)((r0 >> 3) * 512 + j0 + (r0 & 7)) * 512;
        const float* rowB = Whh + (size_t)((((r0 + 8) >> 3)) * 512 + j0 + ((r0 + 8) & 7)) * 512;
        #pragma unroll
        for (int kt = 0; kt < 16; kt++) {
            int kb = kh * 256 + kt * 16 + 2 * c;
            afrag[kt][0] = pack_h2(rowA[kb],     rowA[kb + 1]);
            afrag[kt][1] = pack_h2(rowB[kb],     rowB[kb + 1]);
            afrag[kt][2] = pack_h2(rowA[kb + 8], rowA[kb + 9]);
            afrag[kt][3] = pack_h2(rowB[kb + 8], rowB[kb + 9]);
        }
    }

    for (int i = tid; i < 256 * HP; i += 512) ht2s[i] = 0u;

    const int fb = tid >> 3;
    const int fj = tid & 7;
    float c_state = 0.f;

    unsigned* cnt = &g_cnt[dir][0];
    const float* xg_base = &g_xg[dir][0][fb & 31][j0 + fj];
    float* out_base = out + (size_t)(fb & 31) * (TLEN * 1024) + dir * 512 + j0 + fj;
    uint32_t* h2_base0 = &g_h2[0][dir][(j0 + fj) >> 1][fb & 31];
    uint32_t* h2_base1 = &g_h2[1][dir][(j0 + fj) >> 1][fb & 31];

    __syncthreads();

    for (int s = 0; s < 512; s++) {
        const int t = dir ? (511 - s) : s;

        float xi = 0.f, xf = 0.f, xgv = 0.f, xo = 0.f;
        if (tid < 256) {
            const float* xgp = xg_base + (size_t)t * (BAT * G4);
            xi  = __ldcs(xgp);
            xf  = __ldcs(xgp + 512);
            xgv = __ldcs(xgp + 1024);
            xo  = __ldcs(xgp + 1536);
        }

        float d0 = 0.f, d1 = 0.f, d2 = 0.f, d3 = 0.f;
        float e0 = 0.f, e1 = 0.f, e2 = 0.f, e3 = 0.f;
        #pragma unroll
        for (int kt = 0; kt < 16; kt += 2) {
            int kp0 = kh * 128 + kt * 8;
            uint32_t b0 = ht2s[(kp0 + c) * HP + wn * 8 + g];
            uint32_t b1 = ht2s[(kp0 + 4 + c) * HP + wn * 8 + g];
            mma16816(d0, d1, d2, d3,
                     afrag[kt][0], afrag[kt][1], afrag[kt][2], afrag[kt][3], b0, b1);
            int kp1 = kp0 + 8;
            uint32_t b2 = ht2s[(kp1 + c) * HP + wn * 8 + g];
            uint32_t b3 = ht2s[(kp1 + 4 + c) * HP + wn * 8 + g];
            mma16816(e0, e1, e2, e3,
                     afrag[kt + 1][0], afrag[kt + 1][1], afrag[kt + 1][2], afrag[kt + 1][3], b2, b3);
        }

        {
            float* rp = red + kh * (32 * RP2) + (wm * 16 + g) * RP2 + wn * 8 + 2 * c;
            *(float2*)rp             = make_float2(d0 + e0, d1 + e1);
            *(float2*)(rp + 8 * RP2) = make_float2(d2 + e2, d3 + e3);
        }
        __syncthreads();

        float hval = 0.f;
        if (tid < 256) {
            float dd[4];
            #pragma unroll
            for (int gate = 0; gate < 4; gate++) {
                int off = (gate * 8 + fj) * RP2 + fb;
                dd[gate] = red[off] + red[32 * RP2 + off];
            }
            float ig = fsigmoid(xi  + dd[0]);
            float fg = fsigmoid(xf  + dd[1]);
            float gg = ftanh(xgv + dd[2]);
            float og = fsigmoid(xo  + dd[3]);
            c_state = fg * c_state + ig * gg;
            hval = og * ftanh(c_state);

            if (s < 511) {
                float hpart = __shfl_xor_sync(0xffffffffu, hval, 1);
                if ((fj & 1) == 0) {
                    uint32_t v = pack_h2(hval, hpart);
                    *((s & 1) ? h2_base1 : h2_base0) = v;
                }
            }
        }

        if (s < 511) {
            __syncthreads();
            if (tid == 0) red_add_release(cnt);

            if (tid < 256)
                out_base[(size_t)t * 1024] = hval;

            if (tid == 0) {
                const unsigned tgt = (unsigned)((s + 1) * NBLK_DIR);
                while ((int)(ld_acquire(cnt) - tgt) < 0) { }
            }
            __syncthreads();

            const uint32_t* src = &g_h2[s & 1][dir][0][0];
            #pragma unroll
            for (int i = 0; i < 16; i++) {
                int kp = warp * 16 + i;
                uint32_t v = __ldcg(&src[kp * 32 + lane]);
                ht2s[kp * HP + lane] = v;
            }
            __syncthreads();
        } else {
            if (tid < 256)
                out_base[(size_t)t * 1024] = hval;
        }
    }
}

// ----------------------------------------------------------------------------
// Launch
// ----------------------------------------------------------------------------
extern "C" void kernel_launch(void* const* d_in, const int* in_sizes, int n_in,
                              void* d_out, int out_size)
{
    (void)in_sizes; (void)n_in; (void)out_size;
    const float* x     = (const float*)d_in[0];
    const float* Wih_f = (const float*)d_in[1];
    const float* Whh_f = (const float*)d_in[2];
    const float* bih_f = (const float*)d_in[3];
    const float* bhh_f = (const float*)d_in[4];
    const float* Wih_b = (const float*)d_in[5];
    const float* Whh_b = (const float*)d_in[6];
    const float* bih_b = (const float*)d_in[7];
    const float* bhh_b = (const float*)d_in[8];
    float* out = (float*)d_out;

    static bool attr_set = false;
    if (!attr_set) {
        cudaFuncSetAttribute(lstm_scan_kernel,
                             cudaFuncAttributeMaxDynamicSharedMemorySize,
                             SMEM_WORDS * (int)sizeof(uint32_t));
        cudaFuncSetAttribute(gemm_xg_tc_kernel,
                             cudaFuncAttributeMaxDynamicSharedMemorySize,
                             GSM_BYTES);
        attr_set = true;
    }

    cvt_kernel<<<2560, 256>>>(x, Wih_f, Wih_b);
    dim3 ggrid(16, 128, 2);
    gemm_xg_tc_kernel<<<ggrid, 256, GSM_BYTES>>>(bih_f, bhh_f, bih_b, bhh_b);
    lstm_scan_kernel<<<NBLK, 512, SMEM_WORDS * sizeof(uint32_t)>>>(Whh_f, Whh_b, out);
}